// round 4
// baseline (speedup 1.0000x reference)
#include <cuda_runtime.h>

// FlowNetC correlation: out[b, dy*21+dx, y, x] =
//   (1/256) * sum_c in1[b,c,y,x] * in2[b,c, y+2*dy-20, x+2*dx-20]   (zero-padded)
//
// Blocking: each CTA keyed on (b, 4-row same-parity y-group, in2 row r).
// r = y0 + 2*ri - 20 serves outputs (y = y0+2*yr, dy = ri - yr), yr = 0..3.
// Row pairs packed into fma.rn.f32x2 -> 2 lane-FMAs per issue slot.

#define CCH 256
#define HD  96
#define WD  128
#define NDX 21
#define KC  32       // channels per smem chunk
#define PADW 168     // 128 + 2*20 padded columns

__device__ __forceinline__ unsigned long long pk2(float lo, float hi) {
    unsigned long long r;
    asm("mov.b64 %0, {%1, %2};" : "=l"(r) : "f"(lo), "f"(hi));
    return r;
}
__device__ __forceinline__ void upk2(unsigned long long v, float& lo, float& hi) {
    asm("mov.b64 {%0, %1}, %2;" : "=f"(lo), "=f"(hi) : "l"(v));
}
__device__ __forceinline__ unsigned long long ffma2(unsigned long long a,
                                                    unsigned long long b,
                                                    unsigned long long c) {
    unsigned long long d;
    asm("fma.rn.f32x2 %0, %1, %2, %3;" : "=l"(d) : "l"(a), "l"(b), "l"(c));
    return d;
}

__global__ __launch_bounds__(128, 3)
void corr_kernel(const float* __restrict__ in1,
                 const float* __restrict__ in2,
                 float* __restrict__ out)
{
    __shared__ float s2[KC][PADW];

    const int ri  = blockIdx.x;        // 0..23  -> r = y0 + 2*ri - 20
    const int grp = blockIdx.y;        // 0..23  -> parity + row group
    const int b   = blockIdx.z;        // 0..7
    const int p   = grp & 1;
    const int gi  = grp >> 1;          // 0..11
    const int y0  = p + 8 * gi;        // rows {y0, y0+2, y0+4, y0+6}
    const int x   = threadIdx.x;       // 0..127 == output column
    const int r   = y0 + 2 * ri - 20;  // in2 source row (unpadded coords)

    // accA packs rows (yr=0, yr=1); accB packs rows (yr=2, yr=3)
    unsigned long long accA[NDX], accB[NDX];
#pragma unroll
    for (int d = 0; d < NDX; d++) { accA[d] = 0ull; accB[d] = 0ull; }

    const bool rvalid = (r >= 0) && (r < HD);   // block-uniform

    if (rvalid) {
        const float* in2r = in2 + ((b * CCH) * HD + r) * WD;        // + c*HD*WD
        const float* in1b = in1 + ((b * CCH) * HD + y0) * WD + x;   // + c*HD*WD + yr*2*WD

        const int warp = threadIdx.x >> 5;
        const int lane = threadIdx.x & 31;

        // One-time halo zero: cols [0,20) and [148,168) of every row are
        // constant zero across all channel chunks.
        for (int i = threadIdx.x; i < KC * 20; i += 128) {
            const int cc = i / 20, col = i % 20;
            s2[cc][col]       = 0.0f;
            s2[cc][148 + col] = 0.0f;
        }

        for (int c0 = 0; c0 < CCH; c0 += KC) {
            __syncthreads();
            // Interior fill: s2[cc][20 + j] <- in2r[j], j in [0,128).
            // 32 lanes x 1 LDG.128/STS.128 per channel row; 8 rows per warp.
            for (int cc = warp; cc < KC; cc += 4) {
                const float4* src4 = (const float4*)(in2r + (c0 + cc) * (HD * WD));
                ((float4*)(s2[cc] + 20))[lane] = src4[lane];
            }
            __syncthreads();

#pragma unroll 2
            for (int cc = 0; cc < KC; cc++) {
                const float* a_base = in1b + (c0 + cc) * (HD * WD);
                const float a0 = __ldg(a_base);
                const float a1 = __ldg(a_base + 2 * WD);
                const float a2 = __ldg(a_base + 4 * WD);
                const float a3 = __ldg(a_base + 6 * WD);
                const unsigned long long aA = pk2(a0, a1);
                const unsigned long long aB = pk2(a2, a3);

#pragma unroll
                for (int d = 0; d < NDX; d++) {
                    const float v = s2[cc][x + 2 * d];       // conflict-free LDS
                    const unsigned long long v2 = pk2(v, v); // broadcast pack
                    accA[d] = ffma2(aA, v2, accA[d]);
                    accB[d] = ffma2(aB, v2, accB[d]);
                }
            }
        }
    }

    // Writeout: zeros when r out of range; each output written by exactly one block.
    const float scale = 1.0f / 256.0f;
#pragma unroll
    for (int pr = 0; pr < 2; pr++) {
#pragma unroll
        for (int half = 0; half < 2; half++) {
            const int yr = 2 * pr + half;
            const int dy = ri - yr;
            if (dy < 0 || dy > 20) continue;
            const int y = y0 + 2 * yr;
            float* o = out + ((b * (NDX * NDX) + dy * NDX) * HD + y) * WD + x;
#pragma unroll
            for (int d = 0; d < NDX; d++) {
                float lo, hi;
                upk2(pr == 0 ? accA[d] : accB[d], lo, hi);
                o[d * (HD * WD)] = (half == 0 ? lo : hi) * scale;
            }
        }
    }
}

extern "C" void kernel_launch(void* const* d_in, const int* in_sizes, int n_in,
                              void* d_out, int out_size)
{
    (void)in_sizes; (void)n_in; (void)out_size;
    const float* in1 = (const float*)d_in[0];
    const float* in2 = (const float*)d_in[1];
    float* out = (float*)d_out;

    dim3 grid(24, 24, 8);   // (ri, parity*12+group, batch)
    dim3 block(128);
    corr_kernel<<<grid, block>>>(in1, in2, out);
}

// round 8
// speedup vs baseline: 1.0762x; 1.0762x over previous
#include <cuda_runtime.h>

// FlowNetC correlation: out[b, dy*21+dx, y, x] =
//   (1/256) * sum_c in1[b,c,y,x] * in2[b,c, y+2*dy-20, x+2*dx-20]   (zero-padded)
//
// 8-row blocking: CTA keyed on (b, 8-row same-parity group y0=p+16*gi, ri).
// in2 row r = y0 + 2*ri - 20 serves rows t=0..7 (y = y0+2t) with dy = ri - t.
// Each smem value feeds up to 8 rows -> 0.5 B smem per lane-FMA (LDS = fma/2).
// Row pairs packed into fma.rn.f32x2. Valid pair range [KMIN,KMAX] is
// block-uniform -> templated mainloop, ~5% wasted FMAs.

#define CCH 256
#define HD  96
#define WD  128
#define NDX 21
#define KC  32       // channels per smem chunk
#define PADW 168     // 128 + 2*20 padded columns

typedef unsigned long long u64;

__device__ __forceinline__ u64 pk2(float lo, float hi) {
    u64 r;
    asm("mov.b64 %0, {%1, %2};" : "=l"(r) : "f"(lo), "f"(hi));
    return r;
}
__device__ __forceinline__ void upk2(u64 v, float& lo, float& hi) {
    asm("mov.b64 {%0, %1}, %2;" : "=f"(lo), "=f"(hi) : "l"(v));
}
__device__ __forceinline__ u64 ffma2(u64 a, u64 b, u64 c) {
    u64 d;
    asm("fma.rn.f32x2 %0, %1, %2, %3;" : "=l"(d) : "l"(a), "l"(b), "l"(c));
    return d;
}

// Mainloop specialized on the valid row-pair range [KMIN, KMAX] (block-uniform).
// Pair k covers rows t = 2k, 2k+1 (y = y0+4k, y0+4k+2).
template<int KMIN, int KMAX>
__device__ __forceinline__ void run_main(float s2[KC][PADW],
                                         const float* __restrict__ in2r,
                                         const float* __restrict__ in1b,
                                         u64 (&acc)[4][NDX],
                                         int x, int warp, int lane)
{
    // One-time halo zero: cols [0,20) and [148,168) constant across chunks.
#pragma unroll
    for (int i = 0; i < 5; i++) {
        const int idx = i * 128 + warp * 32 + lane;   // 640 = KC*20
        const int cc = idx / 20, col = idx % 20;
        s2[cc][col]       = 0.0f;
        s2[cc][148 + col] = 0.0f;
    }

    for (int c0 = 0; c0 < CCH; c0 += KC) {
        __syncthreads();
        // Interior fill: s2[cc][20+j] <- in2r[j]; 1 LDG.128/STS.128 per lane-row.
#pragma unroll
        for (int i = 0; i < KC / 4; i++) {
            const int cc = warp + 4 * i;
            const float4* src4 = (const float4*)(in2r + (c0 + cc) * (HD * WD));
            ((float4*)(s2[cc] + 20))[lane] = src4[lane];
        }
        __syncthreads();

#pragma unroll 2
        for (int cc = 0; cc < KC; cc++) {
            const float* a_base = in1b + (c0 + cc) * (HD * WD);
            u64 aP[4];
#pragma unroll
            for (int k = KMIN; k <= KMAX; k++) {
                const float alo = __ldg(a_base + (4 * k)     * WD); // row t=2k
                const float ahi = __ldg(a_base + (4 * k + 2) * WD); // row t=2k+1
                aP[k] = pk2(alo, ahi);
            }
#pragma unroll
            for (int d = 0; d < NDX; d++) {
                const float v = s2[cc][x + 2 * d];   // conflict-free LDS
                const u64 v2 = pk2(v, v);            // broadcast pack
#pragma unroll
                for (int k = KMIN; k <= KMAX; k++)
                    acc[k][d] = ffma2(aP[k], v2, acc[k][d]);
            }
        }
    }
}

__global__ __launch_bounds__(128, 2)
void corr_kernel(const float* __restrict__ in1,
                 const float* __restrict__ in2,
                 float* __restrict__ out)
{
    __shared__ float s2[KC][PADW];

    const int ri  = blockIdx.x;        // 0..27
    const int grp = blockIdx.y;        // 0..11
    const int b   = blockIdx.z;        // 0..7
    const int p   = grp & 1;
    const int gi  = grp >> 1;          // 0..5
    const int y0  = p + 16 * gi;       // rows {y0, y0+2, ..., y0+14}
    const int x   = threadIdx.x;       // 0..127 == output column
    const int r   = y0 + 2 * ri - 20;  // in2 source row (unpadded coords)

    u64 acc[4][NDX];
#pragma unroll
    for (int k = 0; k < 4; k++)
#pragma unroll
        for (int d = 0; d < NDX; d++) acc[k][d] = 0ull;

    const bool rvalid = (r >= 0) && (r < HD);   // block-uniform

    if (rvalid) {
        const float* in2r = in2 + ((b * CCH) * HD + r) * WD;
        const float* in1b = in1 + ((b * CCH) * HD + y0) * WD + x;
        const int warp = threadIdx.x >> 5;
        const int lane = threadIdx.x & 31;

        // Pair k useful iff ri in [2k, 2k+21] -> contiguous [kmin, kmax].
        const int kmax = (ri >> 1) > 3 ? 3 : (ri >> 1);
        const int kmin = (ri - 20) > 0 ? ((ri - 20) >> 1) : 0;

        if (kmax == 3) {
            if      (kmin == 0) run_main<0,3>(s2, in2r, in1b, acc, x, warp, lane);
            else if (kmin == 1) run_main<1,3>(s2, in2r, in1b, acc, x, warp, lane);
            else if (kmin == 2) run_main<2,3>(s2, in2r, in1b, acc, x, warp, lane);
            else                run_main<3,3>(s2, in2r, in1b, acc, x, warp, lane);
        } else if (kmax == 2)   run_main<0,2>(s2, in2r, in1b, acc, x, warp, lane);
        else if   (kmax == 1)   run_main<0,1>(s2, in2r, in1b, acc, x, warp, lane);
        else                    run_main<0,0>(s2, in2r, in1b, acc, x, warp, lane);
    }

    // Writeout: rows t=0..7, dy = ri - t when in [0,20]; zeros if !rvalid.
    const float scale = 1.0f / 256.0f;
#pragma unroll
    for (int t = 0; t < 8; t++) {
        const int dy = ri - t;
        if (dy < 0 || dy > 20) continue;
        const int y = y0 + 2 * t;
        float* o = out + ((b * (NDX * NDX) + dy * NDX) * HD + y) * WD + x;
#pragma unroll
        for (int d = 0; d < NDX; d++) {
            float lo, hi;
            upk2(acc[t >> 1][d], lo, hi);
            o[d * (HD * WD)] = ((t & 1) == 0 ? lo : hi) * scale;
        }
    }
}

extern "C" void kernel_launch(void* const* d_in, const int* in_sizes, int n_in,
                              void* d_out, int out_size)
{
    (void)in_sizes; (void)n_in; (void)out_size;
    const float* in1 = (const float*)d_in[0];
    const float* in2 = (const float*)d_in[1];
    float* out = (float*)d_out;

    dim3 grid(28, 12, 8);   // (ri, parity*6+group, batch)
    dim3 block(128);
    corr_kernel<<<grid, block>>>(in1, in2, out);
}